// round 15
// baseline (speedup 1.0000x reference)
#include <cuda_runtime.h>
#include <cuda_fp16.h>

// KANN_31379031064675 — 2-layer LagrangeKANN.
// R15 = R14 with the SMEM size fixed (T2b is 4096 half2 = 16 KB; total 112 KB,
// not 104 — the R14 crash was the build overrunning the allocation).
// Build: tables converted DIRECTLY from global (L2-resident after wave 1),
// ONE __syncthreads; each warp's x load issued first so DRAM latency hides
// under the build. Main loop = R13 (validated): lane owns one sample, walks
// width pairs (w, w+32); monomial cubic tables; T2 split precision 12 B/width
// (Chebyshev-compensated half2 {a2,a3}); saturate-magic element floor.

__device__ __forceinline__ float magic_fma(float s) {
    float y;
    asm("fma.rn.f32 %0, %1, %2, %3;" : "=f"(y)
        : "f"(s), "f"(63.0f), "f"(8388608.0f));
    return y;
}

__global__ void __launch_bounds__(896, 1) kann_kernel(
    const float* __restrict__ x,
    const float* __restrict__ w_inner,
    const float* __restrict__ w_outer,
    float* __restrict__ out, int n)
{
    extern __shared__ float smem[];
    float*   T1f = smem;                        // float4 idx = e*64 + k   (64 KB)
    float*   T2a = smem + 16384;                // float2 idx = e*64 + k   (32 KB)
    __half2* T2b = (__half2*)(smem + 24576);    // half2  idx = e*64 + k   (16 KB)

    const int tid = threadIdx.x;
    const int nt = blockDim.x;
    const int lane = tid & 31;
    const int wid = tid >> 5;
    const int gwarp = wid * gridDim.x + blockIdx.x;  // spread tail-idle warps
    const int ngroups = n >> 5;
    const bool active = gwarp < ngroups;
    const int base = gwarp << 5;

    // ---- prefetch this warp's sample before the build (hide DRAM latency) ----
    float xv = 0.0f;
    if (active) xv = x[base + lane];

    // ---------------- build (direct from global, 1 sync) ----------------
    // monomial conversion: u_j = c_j W_j, c = {-9/16, 27/16, -27/16, 9/16}
    //   a3 = u0+u1+u2+u3 ; a2 = (u3-u0)+(u2-u1)/3
    //   a1 = -(u1+u2)-(u0+u3)/9 ; a0 = (u1-u2)/3+(u0-u3)/9
    for (int f = tid; f < 4096; f += nt) {
        int k = f & 63, e = f >> 6;
        const float* wp = w_inner + k * 193 + 3 * e;
        float u0 = -0.5625f * wp[0], u1 = 1.6875f * wp[1];
        float u2 = -1.6875f * wp[2], u3 = 0.5625f * wp[3];
        float a3 = (u0 + u1) + (u2 + u3);
        float a2 = (u3 - u0) + (1.0f / 3.0f) * (u2 - u1);
        float a1 = -(u1 + u2) - (1.0f / 9.0f) * (u0 + u3);
        float a0 = (1.0f / 3.0f) * (u1 - u2) + (1.0f / 9.0f) * (u0 - u3);
        ((float4*)T1f)[f] = make_float4(a0, a1, a2, a3);
    }
    for (int f = tid; f < 4096; f += nt) {
        int k = f & 63, e = f >> 6;
        const float* wp = w_outer + k * 193 + 3 * e;
        float u0 = -0.5625f * wp[0], u1 = 1.6875f * wp[1];
        float u2 = -1.6875f * wp[2], u3 = 0.5625f * wp[3];
        float a3 = (u0 + u1) + (u2 + u3);
        float a2 = (u3 - u0) + (1.0f / 3.0f) * (u2 - u1);
        float a1 = -(u1 + u2) - (1.0f / 9.0f) * (u0 + u3);
        float a0 = (1.0f / 3.0f) * (u1 - u2) + (1.0f / 9.0f) * (u0 - u3);
        __half h2 = __float2half_rn(a2);
        __half h3 = __float2half_rn(a3);
        float r2 = a2 - __half2float(h2);
        float r3 = a3 - __half2float(h3);
        // Chebyshev residual folding: xt^2 ~ 1/2, xt^3 ~ (3/4)xt on [-1,1]
        ((float2*)T2a)[f] = make_float2(a0 + 0.5f * r2, fmaf(0.75f, r3, a1));
        T2b[f] = __halves2half2(h2, h3);
    }
    __syncthreads();

    // ---------------- main (each warp: one 32-sample group) ----------------
    if (active) {
        const char* __restrict__ T1p  = (const char*)T1f;
        const char* __restrict__ T2ap = (const char*)T2a;
        const __half2* __restrict__ T2bp = T2b;

        // per-group layer-1 params (sample fixed per lane)
        const float s1 = __saturatef(fmaf(xv, 64.0f / 63.0f, -0.5f / 63.0f));
        const float y1 = magic_fma(s1);
        const int b1 = (__float_as_int(y1) & 63) << 10;   // byte offset, in-bounds
        const float xt = fmaf(xv, 128.0f, fmaf(y1, -2.0f, 16777215.0f));

        float accA = 0.0f, accB = 0.0f;

        #pragma unroll 8
        for (int i = 0; i < 32; ++i) {
            const int w = (lane + i) & 31;

            // layer 1: 2 LDS.128 + 6 FMA (shared xt), widths (w, w+32)
            const float4 cA = *(const float4*)(T1p + b1 + (w << 4));
            const float4 cB = *(const float4*)(T1p + b1 + 512 + (w << 4));
            const float tA = fmaf(fmaf(fmaf(cA.w, xt, cA.z), xt, cA.y), xt, cA.x);
            const float tB = fmaf(fmaf(fmaf(cB.w, xt, cB.z), xt, cB.y), xt, cB.x);

            // layer 2, width w: 8B fp32 {a0',a1'} + 4B half2 {a2,a3}
            const float sA = __saturatef(fmaf(tA, 64.0f / 63.0f, -0.5f / 63.0f));
            const float yA = magic_fma(sA);
            const int eA = __float_as_int(yA) & 63;
            const float xtA = fmaf(tA, 128.0f, fmaf(yA, -2.0f, 16777215.0f));
            const float2 abA = *(const float2*)(T2ap + (eA << 9) + (w << 3));
            const float2 cdA = __half22float2(T2bp[(eA << 6) + w]);
            accA += fmaf(fmaf(fmaf(cdA.y, xtA, cdA.x), xtA, abA.y), xtA, abA.x);

            // layer 2, width w+32
            const float sB = __saturatef(fmaf(tB, 64.0f / 63.0f, -0.5f / 63.0f));
            const float yB = magic_fma(sB);
            const int eB = __float_as_int(yB) & 63;
            const float xtB = fmaf(tB, 128.0f, fmaf(yB, -2.0f, 16777215.0f));
            const float2 abB = *(const float2*)(T2ap + (eB << 9) + 256 + (w << 3));
            const float2 cdB = __half22float2(T2bp[(eB << 6) + 32 + w]);
            accB += fmaf(fmaf(fmaf(cdB.y, xtB, cdB.x), xtB, abB.y), xtB, abB.x);
        }
        out[base + lane] = accA + accB;
    }
}

extern "C" void kernel_launch(void* const* d_in, const int* in_sizes, int n_in,
                              void* d_out, int out_size) {
    const float* x  = (const float*)d_in[0];
    const float* wi = (const float*)d_in[1];
    const float* wo = (const float*)d_in[2];
    float* out = (float*)d_out;
    const int n = in_sizes[0];

    const int smem_bytes = 28672 * sizeof(float);  // 112 KB: 64K T1 + 32K T2a + 16K T2b
    cudaFuncSetAttribute(kann_kernel, cudaFuncAttributeMaxDynamicSharedMemorySize,
                         smem_bytes);
    kann_kernel<<<148, 896, smem_bytes>>>(x, wi, wo, out, n);
}

// round 16
// speedup vs baseline: 1.2359x; 1.2359x over previous
#include <cuda_runtime.h>

// KANN_31379031064675 — 2-layer LagrangeKANN. Two-kernel split:
//   K1: convert w_inner/w_outer -> monomial cubic float4 tables ONCE into a
//       __device__ global buffer (128 KB scratch; no allocation).
//   K2: per-CTA "build" is a pure coalesced 128 KB copy (no conversion), then
//       the validated main loop: lane owns one sample per 32-group, walks
//       width pairs (w, w+32); 1 LDS.128 + 3-FMA Horner per layer eval;
//       saturate-magic element floor (s=sat(fma(t,64/63,-.5/63));
//       y=asm_fma(s,63,2^23); e=bits(y)&63; xt=fma(t,128,fma(y,-2,2^24-1))).

__device__ float4 g_tab[8192];   // [0,4096) = T1, [4096,8192) = T2

__device__ __forceinline__ float magic_fma(float s) {
    float y;
    asm("fma.rn.f32 %0, %1, %2, %3;" : "=f"(y)
        : "f"(s), "f"(63.0f), "f"(8388608.0f));
    return y;
}

__global__ void __launch_bounds__(512, 1) build_kernel(
    const float* __restrict__ w_inner,
    const float* __restrict__ w_outer)
{
    const int f = blockIdx.x * blockDim.x + threadIdx.x;   // 0..8191
    if (f >= 8192) return;
    const float* __restrict__ src = (f < 4096) ? w_inner : w_outer;
    const int idx = f & 4095;
    const int k = idx & 63, e = idx >> 6;
    const float* wp = src + k * 193 + 3 * e;
    // u_j = c_j W_j, c = {-9/16, 27/16, -27/16, 9/16}; monomial coefficients:
    float u0 = -0.5625f * wp[0], u1 = 1.6875f * wp[1];
    float u2 = -1.6875f * wp[2], u3 = 0.5625f * wp[3];
    float a3 = (u0 + u1) + (u2 + u3);
    float a2 = (u3 - u0) + (1.0f / 3.0f) * (u2 - u1);
    float a1 = -(u1 + u2) - (1.0f / 9.0f) * (u0 + u3);
    float a0 = (1.0f / 3.0f) * (u1 - u2) + (1.0f / 9.0f) * (u0 - u3);
    g_tab[f] = make_float4(a0, a1, a2, a3);
}

__global__ void __launch_bounds__(896, 1) kann_kernel(
    const float* __restrict__ x,
    float* __restrict__ out, int n)
{
    extern __shared__ float smem[];

    const int tid = threadIdx.x;
    const int nt = blockDim.x;
    const int lane = tid & 31;
    const int wid = tid >> 5;
    const int gwarp = wid * gridDim.x + blockIdx.x;  // spread tail-idle warps
    const int ngroups = n >> 5;
    const bool active = gwarp < ngroups;
    const int base = gwarp << 5;

    // prefetch this warp's samples; latency hides under the table copy
    float xv = 0.0f;
    if (active) xv = x[base + lane];

    // ---- build = coalesced copy of the pre-converted tables (one sync) ----
    {
        float4* sm = (float4*)smem;
        #pragma unroll
        for (int r = 0; r < 10; ++r) {
            int f = tid + r * 896;
            if (f < 8192) sm[f] = g_tab[f];
        }
    }
    __syncthreads();

    if (active) {
        const char* __restrict__ T1p = (const char*)smem;            // e*1024 + w*16
        const char* __restrict__ T2p = (const char*)smem + 65536;    // e*1024 + w*16

        // per-group layer-1 params (sample fixed per lane)
        const float s1 = __saturatef(fmaf(xv, 64.0f / 63.0f, -0.5f / 63.0f));
        const float y1 = magic_fma(s1);
        const int b1 = (__float_as_int(y1) & 63) << 10;   // byte offset, in-bounds
        const float xt = fmaf(xv, 128.0f, fmaf(y1, -2.0f, 16777215.0f));

        float accA = 0.0f, accB = 0.0f;

        #pragma unroll 8
        for (int i = 0; i < 32; ++i) {
            const int w = (lane + i) & 31;

            // layer 1: 2 LDS.128 + 6 FMA (shared xt), widths (w, w+32)
            const float4 cA = *(const float4*)(T1p + b1 + (w << 4));
            const float4 cB = *(const float4*)(T1p + b1 + 512 + (w << 4));
            const float tA = fmaf(fmaf(fmaf(cA.w, xt, cA.z), xt, cA.y), xt, cA.x);
            const float tB = fmaf(fmaf(fmaf(cB.w, xt, cB.z), xt, cB.y), xt, cB.x);

            // layer 2, width w
            const float sA = __saturatef(fmaf(tA, 64.0f / 63.0f, -0.5f / 63.0f));
            const float yA = magic_fma(sA);
            const int eAb = (__float_as_int(yA) & 63) << 10;
            const float xtA = fmaf(tA, 128.0f, fmaf(yA, -2.0f, 16777215.0f));
            const float4 dA = *(const float4*)(T2p + eAb + (w << 4));
            accA += fmaf(fmaf(fmaf(dA.w, xtA, dA.z), xtA, dA.y), xtA, dA.x);

            // layer 2, width w+32
            const float sB = __saturatef(fmaf(tB, 64.0f / 63.0f, -0.5f / 63.0f));
            const float yB = magic_fma(sB);
            const int eBb = (__float_as_int(yB) & 63) << 10;
            const float xtB = fmaf(tB, 128.0f, fmaf(yB, -2.0f, 16777215.0f));
            const float4 dB = *(const float4*)(T2p + eBb + 512 + (w << 4));
            accB += fmaf(fmaf(fmaf(dB.w, xtB, dB.z), xtB, dB.y), xtB, dB.x);
        }
        out[base + lane] = accA + accB;
    }
}

extern "C" void kernel_launch(void* const* d_in, const int* in_sizes, int n_in,
                              void* d_out, int out_size) {
    const float* x  = (const float*)d_in[0];
    const float* wi = (const float*)d_in[1];
    const float* wo = (const float*)d_in[2];
    float* out = (float*)d_out;
    const int n = in_sizes[0];

    build_kernel<<<16, 512>>>(wi, wo);

    const int smem_bytes = 8192 * sizeof(float4);  // 128 KB
    cudaFuncSetAttribute(kann_kernel, cudaFuncAttributeMaxDynamicSharedMemorySize,
                         smem_bytes);
    kann_kernel<<<148, 896, smem_bytes>>>(x, out, n);
}

// round 17
// speedup vs baseline: 1.2431x; 1.0059x over previous
#include <cuda_runtime.h>
#include <cuda_fp16.h>

// KANN_31379031064675 — 2-layer LagrangeKANN. Two-kernel split:
//   K1 (tiny): converts w_inner/w_outer ONCE into monomial cubic tables in a
//       __device__ global buffer, already in the split-precision layout:
//         g_t1 : float4 {a0,a1,a2,a3}            (T1 stays fp32: x128 error amp)
//         g_t2a: float2 {a0',a1'} fp32            (Chebyshev-compensated)
//         g_t2b: half2  {a2,a3}
//   K2: per-CTA build = pure coalesced 112 KB copy (one sync), x prefetched
//       before it; then the validated main loop (lane owns one sample per
//       32-group, walks width pairs (w, w+32); Horner evals; saturate-magic
//       element floor). T2 split precision = 14 smem wavefronts/warp-iter
//       instead of 16 (measured rel_err 2.5e-4 in R13).

__device__ float4  g_t1[4096];
__device__ float2  g_t2a[4096];
__device__ __half2 g_t2b[4096];

__device__ __forceinline__ float magic_fma(float s) {
    float y;
    asm("fma.rn.f32 %0, %1, %2, %3;" : "=f"(y)
        : "f"(s), "f"(63.0f), "f"(8388608.0f));
    return y;
}

__global__ void __launch_bounds__(512, 1) build_kernel(
    const float* __restrict__ w_inner,
    const float* __restrict__ w_outer)
{
    const int f = blockIdx.x * blockDim.x + threadIdx.x;   // 0..8191
    if (f >= 8192) return;
    const bool is_t2 = f >= 4096;
    const int idx = f & 4095;
    const int k = idx & 63, e = idx >> 6;
    const float* wp = (is_t2 ? w_outer : w_inner) + k * 193 + 3 * e;
    // u_j = c_j W_j, c = {-9/16, 27/16, -27/16, 9/16}; monomial coefficients:
    float u0 = -0.5625f * wp[0], u1 = 1.6875f * wp[1];
    float u2 = -1.6875f * wp[2], u3 = 0.5625f * wp[3];
    float a3 = (u0 + u1) + (u2 + u3);
    float a2 = (u3 - u0) + (1.0f / 3.0f) * (u2 - u1);
    float a1 = -(u1 + u2) - (1.0f / 9.0f) * (u0 + u3);
    float a0 = (1.0f / 3.0f) * (u1 - u2) + (1.0f / 9.0f) * (u0 - u3);
    if (!is_t2) {
        g_t1[idx] = make_float4(a0, a1, a2, a3);
    } else {
        __half h2 = __float2half_rn(a2);
        __half h3 = __float2half_rn(a3);
        float r2 = a2 - __half2float(h2);
        float r3 = a3 - __half2float(h3);
        // Chebyshev residual folding: xt^2 ~ 1/2, xt^3 ~ (3/4)xt on [-1,1]
        g_t2a[idx] = make_float2(a0 + 0.5f * r2, fmaf(0.75f, r3, a1));
        g_t2b[idx] = __halves2half2(h2, h3);
    }
}

__global__ void __launch_bounds__(896, 1) kann_kernel(
    const float* __restrict__ x,
    float* __restrict__ out, int n)
{
    extern __shared__ float smem[];
    // [0,16384)      T1  float4 idx = e*64 + k        (64 KB)
    // [16384,24576)  T2a float2 idx = e*64 + k        (32 KB)
    // [24576,28672)  T2b half2  idx = e*64 + k        (16 KB)

    const int tid = threadIdx.x;
    const int lane = tid & 31;
    const int wid = tid >> 5;
    const int gwarp = wid * gridDim.x + blockIdx.x;  // spread tail-idle warps
    const int ngroups = n >> 5;
    const bool active = gwarp < ngroups;
    const int base = gwarp << 5;

    // prefetch this warp's samples; latency hides under the table copy
    float xv = 0.0f;
    if (active) xv = x[base + lane];

    // ---- build = coalesced copy of pre-converted tables (one sync) ----
    {
        float4* d1 = (float4*)smem;
        #pragma unroll
        for (int r = 0; r < 5; ++r) {
            int f = tid + r * 896;
            if (f < 4096) d1[f] = g_t1[f];
        }
        float4* d2 = (float4*)(smem + 16384);
        const float4* s2 = (const float4*)g_t2a;
        #pragma unroll
        for (int r = 0; r < 3; ++r) {
            int f = tid + r * 896;
            if (f < 2048) d2[f] = s2[f];
        }
        float4* d3 = (float4*)(smem + 24576);
        const float4* s3 = (const float4*)g_t2b;
        #pragma unroll
        for (int r = 0; r < 2; ++r) {
            int f = tid + r * 896;
            if (f < 1024) d3[f] = s3[f];
        }
    }
    __syncthreads();

    if (active) {
        const char* __restrict__ T1p  = (const char*)smem;
        const char* __restrict__ T2ap = (const char*)(smem + 16384);
        const __half2* __restrict__ T2bp = (const __half2*)(smem + 24576);

        // per-group layer-1 params (sample fixed per lane)
        const float s1 = __saturatef(fmaf(xv, 64.0f / 63.0f, -0.5f / 63.0f));
        const float y1 = magic_fma(s1);
        const int b1 = (__float_as_int(y1) & 63) << 10;   // byte offset, in-bounds
        const float xt = fmaf(xv, 128.0f, fmaf(y1, -2.0f, 16777215.0f));

        float accA = 0.0f, accB = 0.0f;

        #pragma unroll 8
        for (int i = 0; i < 32; ++i) {
            const int w = (lane + i) & 31;

            // layer 1: 2 LDS.128 + 6 FMA (shared xt), widths (w, w+32)
            const float4 cA = *(const float4*)(T1p + b1 + (w << 4));
            const float4 cB = *(const float4*)(T1p + b1 + 512 + (w << 4));
            const float tA = fmaf(fmaf(fmaf(cA.w, xt, cA.z), xt, cA.y), xt, cA.x);
            const float tB = fmaf(fmaf(fmaf(cB.w, xt, cB.z), xt, cB.y), xt, cB.x);

            // layer 2, width w: 8B fp32 {a0',a1'} + 4B half2 {a2,a3}
            const float sA = __saturatef(fmaf(tA, 64.0f / 63.0f, -0.5f / 63.0f));
            const float yA = magic_fma(sA);
            const int eA = __float_as_int(yA) & 63;
            const float xtA = fmaf(tA, 128.0f, fmaf(yA, -2.0f, 16777215.0f));
            const float2 abA = *(const float2*)(T2ap + (eA << 9) + (w << 3));
            const float2 cdA = __half22float2(T2bp[(eA << 6) + w]);
            accA += fmaf(fmaf(fmaf(cdA.y, xtA, cdA.x), xtA, abA.y), xtA, abA.x);

            // layer 2, width w+32
            const float sB = __saturatef(fmaf(tB, 64.0f / 63.0f, -0.5f / 63.0f));
            const float yB = magic_fma(sB);
            const int eB = __float_as_int(yB) & 63;
            const float xtB = fmaf(tB, 128.0f, fmaf(yB, -2.0f, 16777215.0f));
            const float2 abB = *(const float2*)(T2ap + (eB << 9) + 256 + (w << 3));
            const float2 cdB = __half22float2(T2bp[(eB << 6) + 32 + w]);
            accB += fmaf(fmaf(fmaf(cdB.y, xtB, cdB.x), xtB, abB.y), xtB, abB.x);
        }
        out[base + lane] = accA + accB;
    }
}

extern "C" void kernel_launch(void* const* d_in, const int* in_sizes, int n_in,
                              void* d_out, int out_size) {
    const float* x  = (const float*)d_in[0];
    const float* wi = (const float*)d_in[1];
    const float* wo = (const float*)d_in[2];
    float* out = (float*)d_out;
    const int n = in_sizes[0];

    build_kernel<<<16, 512>>>(wi, wo);

    const int smem_bytes = 28672 * sizeof(float);  // 112 KB
    cudaFuncSetAttribute(kann_kernel, cudaFuncAttributeMaxDynamicSharedMemorySize,
                         smem_bytes);
    kann_kernel<<<148, 896, smem_bytes>>>(x, out, n);
}